// round 1
// baseline (speedup 1.0000x reference)
#include <cuda_runtime.h>

// Shapes (fixed by the problem)
#define B_   2
#define S_   2048
#define H_   1024
#define NH_  16
#define M_   512
#define D_   64
#define CAT_ (H_ + M_)   // 1536

// ---------------- scratch (static device memory; no allocations allowed) ---
__device__ float g_q  [(long long)B_*S_*H_];
__device__ float g_k  [(long long)B_*S_*H_];
__device__ float g_v  [(long long)B_*S_*H_];
__device__ float g_mq [(long long)B_*S_*M_];
__device__ float g_mk [(long long)B_*S_*M_];
__device__ float g_med[(long long)B_*S_*S_];
__device__ float g_cat[(long long)B_*S_*CAT_];
__device__ float g_x  [(long long)B_*S_*H_];

// ---------------- tiled GEMM bodies (BM=BN=64, BK=16, 256 thr, 4x4/thr) ----
#define BM 64
#define BN 64
#define BK 16

// C = A[M,K] @ B[K,N] (+bias). All dims assumed multiples of tile sizes.
__device__ __forceinline__ void gemm_nn_body(
    const float* __restrict__ A, const float* __restrict__ Bm,
    const float* __restrict__ bias, float* __restrict__ C,
    int K, int lda, int ldb, int ldc)
{
    __shared__ float As[BK][BM + 1];
    __shared__ float Bs[BK][BN + 1];
    const int row0 = blockIdx.y * BM;
    const int col0 = blockIdx.x * BN;
    const int tid = threadIdx.x;
    const int tx = tid & 15, ty = tid >> 4;

    float acc[4][4] = {};
    for (int k0 = 0; k0 < K; k0 += BK) {
        #pragma unroll
        for (int i = tid; i < BM * BK; i += 256) {
            int r = i >> 4, c = i & 15;
            As[c][r] = A[(long long)(row0 + r) * lda + (k0 + c)];
        }
        #pragma unroll
        for (int i = tid; i < BK * BN; i += 256) {
            int r = i >> 6, c = i & 63;
            Bs[r][c] = Bm[(long long)(k0 + r) * ldb + (col0 + c)];
        }
        __syncthreads();
        #pragma unroll
        for (int kk = 0; kk < BK; ++kk) {
            float a[4], b[4];
            #pragma unroll
            for (int i = 0; i < 4; ++i) a[i] = As[kk][ty * 4 + i];
            #pragma unroll
            for (int j = 0; j < 4; ++j) b[j] = Bs[kk][tx * 4 + j];
            #pragma unroll
            for (int i = 0; i < 4; ++i)
                #pragma unroll
                for (int j = 0; j < 4; ++j)
                    acc[i][j] += a[i] * b[j];
        }
        __syncthreads();
    }
    #pragma unroll
    for (int i = 0; i < 4; ++i) {
        int r = row0 + ty * 4 + i;
        #pragma unroll
        for (int j = 0; j < 4; ++j) {
            int c = col0 + tx * 4 + j;
            float val = acc[i][j];
            if (bias) val += bias[c];
            C[(long long)r * ldc + c] = val;
        }
    }
}

// C = alpha * A[M,K] @ B[N,K]^T (+ addScale * Add). Add may be null.
__device__ __forceinline__ void gemm_nt_body(
    const float* __restrict__ A, const float* __restrict__ Bm,
    float* __restrict__ C, int K, int lda, int ldb, int ldc,
    float alpha, const float* __restrict__ Add, int ldadd, float addScale)
{
    __shared__ float As[BK][BM + 1];
    __shared__ float Bs[BK][BN + 1];
    const int row0 = blockIdx.y * BM;
    const int col0 = blockIdx.x * BN;
    const int tid = threadIdx.x;
    const int tx = tid & 15, ty = tid >> 4;

    float acc[4][4] = {};
    for (int k0 = 0; k0 < K; k0 += BK) {
        #pragma unroll
        for (int i = tid; i < BM * BK; i += 256) {
            int r = i >> 4, c = i & 15;
            As[c][r] = A[(long long)(row0 + r) * lda + (k0 + c)];
        }
        #pragma unroll
        for (int i = tid; i < BN * BK; i += 256) {
            int n = i >> 4, c = i & 15;
            Bs[c][n] = Bm[(long long)(col0 + n) * ldb + (k0 + c)];
        }
        __syncthreads();
        #pragma unroll
        for (int kk = 0; kk < BK; ++kk) {
            float a[4], b[4];
            #pragma unroll
            for (int i = 0; i < 4; ++i) a[i] = As[kk][ty * 4 + i];
            #pragma unroll
            for (int j = 0; j < 4; ++j) b[j] = Bs[kk][tx * 4 + j];
            #pragma unroll
            for (int i = 0; i < 4; ++i)
                #pragma unroll
                for (int j = 0; j < 4; ++j)
                    acc[i][j] += a[i] * b[j];
        }
        __syncthreads();
    }
    #pragma unroll
    for (int i = 0; i < 4; ++i) {
        int r = row0 + ty * 4 + i;
        #pragma unroll
        for (int j = 0; j < 4; ++j) {
            int c = col0 + tx * 4 + j;
            float val = acc[i][j] * alpha;
            if (Add) val += addScale * Add[(long long)r * ldadd + c];
            C[(long long)r * ldc + c] = val;
        }
    }
}

// ---------------- kernels ----------------

// Generic batched NN GEMM (linear batch strides in elements)
__global__ void __launch_bounds__(256) k_gemm_nn(
    const float* __restrict__ A, const float* __restrict__ Bm,
    const float* __restrict__ bias, float* __restrict__ C,
    int K, int lda, int ldb, int ldc,
    long long sA, long long sB, long long sC)
{
    int z = blockIdx.z;
    gemm_nn_body(A + (long long)z * sA, Bm + (long long)z * sB, bias,
                 C + (long long)z * sC, K, lda, ldb, ldc);
}

// Generic batched NT GEMM
__global__ void __launch_bounds__(256) k_gemm_nt(
    const float* __restrict__ A, const float* __restrict__ Bm,
    float* __restrict__ C, int K, int lda, int ldb, int ldc,
    long long sA, long long sB, long long sC, float alpha)
{
    int z = blockIdx.z;
    gemm_nt_body(A + (long long)z * sA, Bm + (long long)z * sB,
                 C + (long long)z * sC, K, lda, ldb, ldc,
                 alpha, nullptr, 0, 0.0f);
}

// scores[b,h] = q_h @ k_h^T / 8 + 0.3 * med[b]   (written into probs region)
__global__ void __launch_bounds__(256) k_attn_scores(
    const float* __restrict__ q, const float* __restrict__ k,
    const float* __restrict__ med, float* __restrict__ probs)
{
    int z = blockIdx.z;           // b*NH + h
    int b = z >> 4, h = z & 15;
    const float* A  = q + (long long)b * S_ * H_ + h * D_;
    const float* Bm = k + (long long)b * S_ * H_ + h * D_;
    float*       C  = probs + (long long)z * S_ * S_;
    const float* Add = med + (long long)b * S_ * S_;
    gemm_nt_body(A, Bm, C, D_, H_, H_, S_, 0.125f, Add, S_, 0.3f);
}

// ctx[b,h] = probs[b,h] @ v_h  -> written into cat buffer cols [h*64, h*64+64)
__global__ void __launch_bounds__(256) k_attn_ctx(
    const float* __restrict__ probs, const float* __restrict__ v,
    float* __restrict__ cat)
{
    int z = blockIdx.z;
    int b = z >> 4, h = z & 15;
    const float* A  = probs + (long long)z * S_ * S_;
    const float* Bm = v + (long long)b * S_ * H_ + h * D_;
    float*       C  = cat + (long long)b * S_ * CAT_ + h * D_;
    gemm_nn_body(A, Bm, nullptr, C, S_, S_, H_, CAT_);
}

// in-place row softmax over 2048 cols, one block (256 thr) per row
__global__ void __launch_bounds__(256) k_softmax2048(float* __restrict__ X)
{
    long long row = blockIdx.x;
    float* x = X + row * 2048;
    int tid = threadIdx.x;
    __shared__ float red[256];

    float v[8];
    float m = -1e30f;
    #pragma unroll
    for (int i = 0; i < 8; ++i) {
        v[i] = x[tid + i * 256];
        m = fmaxf(m, v[i]);
    }
    red[tid] = m; __syncthreads();
    for (int s = 128; s > 0; s >>= 1) {
        if (tid < s) red[tid] = fmaxf(red[tid], red[tid + s]);
        __syncthreads();
    }
    m = red[0];
    __syncthreads();

    float sum = 0.0f;
    #pragma unroll
    for (int i = 0; i < 8; ++i) {
        v[i] = __expf(v[i] - m);
        sum += v[i];
    }
    red[tid] = sum; __syncthreads();
    for (int s = 128; s > 0; s >>= 1) {
        if (tid < s) red[tid] += red[tid + s];
        __syncthreads();
    }
    float inv = 1.0f / red[0];
    #pragma unroll
    for (int i = 0; i < 8; ++i) x[tid + i * 256] = v[i] * inv;
}

// out = LayerNorm(x + hs) * g + b, one block (256 thr) per row of 1024
__global__ void __launch_bounds__(256) k_ln_res(
    const float* __restrict__ xin, const float* __restrict__ hs,
    const float* __restrict__ g, const float* __restrict__ be,
    float* __restrict__ out)
{
    long long row = blockIdx.x;
    const float* xr = xin + row * H_;
    const float* hr = hs + row * H_;
    float* orow = out + row * H_;
    int tid = threadIdx.x;
    __shared__ float red[256];

    float v[4];
    float s = 0.0f;
    #pragma unroll
    for (int i = 0; i < 4; ++i) {
        v[i] = xr[tid + i * 256] + hr[tid + i * 256];
        s += v[i];
    }
    red[tid] = s; __syncthreads();
    for (int t = 128; t > 0; t >>= 1) {
        if (tid < t) red[tid] += red[tid + t];
        __syncthreads();
    }
    float mu = red[0] * (1.0f / H_);
    __syncthreads();

    float var = 0.0f;
    #pragma unroll
    for (int i = 0; i < 4; ++i) {
        float d = v[i] - mu;
        var += d * d;
    }
    red[tid] = var; __syncthreads();
    for (int t = 128; t > 0; t >>= 1) {
        if (tid < t) red[tid] += red[tid + t];
        __syncthreads();
    }
    float inv = rsqrtf(red[0] * (1.0f / H_) + 1e-12f);
    #pragma unroll
    for (int i = 0; i < 4; ++i) {
        int c = tid + i * 256;
        orow[c] = (v[i] - mu) * inv * g[c] + be[c];
    }
}

// ---------------- launch ----------------
extern "C" void kernel_launch(void* const* d_in, const int* in_sizes, int n_in,
                              void* d_out, int out_size)
{
    const float* hs  = (const float*)d_in[0];
    const float* mc  = (const float*)d_in[1];
    const float* Wq  = (const float*)d_in[2];  const float* bq  = (const float*)d_in[3];
    const float* Wk  = (const float*)d_in[4];  const float* bk  = (const float*)d_in[5];
    const float* Wv  = (const float*)d_in[6];  const float* bv  = (const float*)d_in[7];
    const float* Wmq = (const float*)d_in[8];  const float* bmq = (const float*)d_in[9];
    const float* Wmk = (const float*)d_in[10]; const float* bmk = (const float*)d_in[11];
    const float* Wc  = (const float*)d_in[12]; const float* bc  = (const float*)d_in[13];
    const float* Wf  = (const float*)d_in[14]; const float* bf  = (const float*)d_in[15];
    const float* lg  = (const float*)d_in[16]; const float* lb  = (const float*)d_in[17];

    float* out   = (float*)d_out;                        // [B,S,H]
    float* probs = out + (long long)B_ * S_ * H_;        // [B,NH,S,S]

    float *q, *k, *v, *mq, *mk, *med, *cat, *x;
    cudaGetSymbolAddress((void**)&q,   g_q);
    cudaGetSymbolAddress((void**)&k,   g_k);
    cudaGetSymbolAddress((void**)&v,   g_v);
    cudaGetSymbolAddress((void**)&mq,  g_mq);
    cudaGetSymbolAddress((void**)&mk,  g_mk);
    cudaGetSymbolAddress((void**)&med, g_med);
    cudaGetSymbolAddress((void**)&cat, g_cat);
    cudaGetSymbolAddress((void**)&x,   g_x);

    const int rows = B_ * S_;   // 4096
    dim3 blk(256);

    // Q, K, V projections  [4096,1024] @ [1024,1024]
    k_gemm_nn<<<dim3(H_ / BN, rows / BM, 1), blk>>>(hs, Wq, bq, q, H_, H_, H_, H_, 0, 0, 0);
    k_gemm_nn<<<dim3(H_ / BN, rows / BM, 1), blk>>>(hs, Wk, bk, k, H_, H_, H_, H_, 0, 0, 0);
    k_gemm_nn<<<dim3(H_ / BN, rows / BM, 1), blk>>>(hs, Wv, bv, v, H_, H_, H_, H_, 0, 0, 0);

    // medical projections  [4096,1024] @ [1024,512]
    k_gemm_nn<<<dim3(M_ / BN, rows / BM, 1), blk>>>(hs, Wmq, bmq, mq, H_, H_, M_, M_, 0, 0, 0);
    k_gemm_nn<<<dim3(M_ / BN, rows / BM, 1), blk>>>(mc, Wmk, bmk, mk, H_, H_, M_, M_, 0, 0, 0);

    // med scores: per-batch mq @ mk^T  [2048,512]x[2048,512]^T -> [2048,2048]
    k_gemm_nt<<<dim3(S_ / BN, S_ / BM, B_), blk>>>(
        mq, mk, med, M_, M_, M_, S_,
        (long long)S_ * M_, (long long)S_ * M_, (long long)S_ * S_, 1.0f);
    k_softmax2048<<<B_ * S_, 256>>>(med);

    // attention scores -> probs region, then softmax in place
    k_attn_scores<<<dim3(S_ / BN, S_ / BM, B_ * NH_), blk>>>(q, k, med, probs);
    k_softmax2048<<<B_ * NH_ * S_, 256>>>(probs);

    // ctx = probs @ v  -> cat[:, 0:1024]
    k_attn_ctx<<<dim3(1, S_ / BM, B_ * NH_), blk>>>(probs, v, cat);

    // clin = ctx @ Wc + bc -> cat[:, 1024:1536]
    k_gemm_nn<<<dim3(M_ / BN, rows / BM, 1), blk>>>(cat, Wc, bc, cat + H_, H_, CAT_, M_, CAT_, 0, 0, 0);

    // final = cat @ Wf + bf  [4096,1536] @ [1536,1024]
    k_gemm_nn<<<dim3(H_ / BN, rows / BM, 1), blk>>>(cat, Wf, bf, x, CAT_, CAT_, H_, H_, 0, 0, 0);

    // residual + layernorm -> out
    k_ln_res<<<rows, 256>>>(x, hs, lg, lb, out);
}

// round 5
// speedup vs baseline: 1.6353x; 1.6353x over previous
#include <cuda_runtime.h>
#include <cstdint>

// Shapes (fixed by the problem)
#define B_   2
#define S_   2048
#define H_   1024
#define NH_  16
#define M_   512
#define D_   64
#define CAT_ (H_ + M_)   // 1536

// ---------------- scratch (static device memory; no allocations allowed) ---
__device__ float g_q  [(long long)B_*S_*H_];
__device__ float g_k  [(long long)B_*S_*H_];
__device__ float g_v  [(long long)B_*S_*H_];
__device__ float g_mq [(long long)B_*S_*M_];
__device__ float g_mk [(long long)B_*S_*M_];
__device__ float g_med[(long long)B_*S_*S_];
__device__ float g_cat[(long long)B_*S_*CAT_];
__device__ float g_x  [(long long)B_*S_*H_];

// ---------------- tf32 helpers ----------------
__device__ __forceinline__ float to_tf32(float f) {
    float r;
    asm("cvt.rna.tf32.f32 %0, %1;" : "=f"(r) : "f"(f));
    return r;
}
__device__ __forceinline__ void mma_tf32(float* d, const float* a, const float* b) {
    asm volatile(
        "mma.sync.aligned.m16n8k8.row.col.f32.tf32.tf32.f32 "
        "{%0,%1,%2,%3}, {%4,%5,%6,%7}, {%8,%9}, {%0,%1,%2,%3};"
        : "+f"(d[0]), "+f"(d[1]), "+f"(d[2]), "+f"(d[3])
        : "r"(__float_as_uint(a[0])), "r"(__float_as_uint(a[1])),
          "r"(__float_as_uint(a[2])), "r"(__float_as_uint(a[3])),
          "r"(__float_as_uint(b[0])), "r"(__float_as_uint(b[1])));
}

// ---------------- smem layout (floats) ----------------
// A tiles: [128][16] padded stride 20 -> 2560 floats each (hi, lo)
// B tiles: [16][64] padded stride 72 -> 1152 floats each (hi, lo)
#define A_ST 20
#define B_ST 72
#define SA_HI 0
#define SA_LO 2560
#define SB_HI 5120
#define SB_LO 6272
#define SMEM_FLOATS 7424   // 29696 bytes

// ---------------- universal 3xTF32 GEMM ----------------
// C[M,N] = alpha * A[M,K] @ op(B) (+bias[col]) (+addScale*Add[row,col])
// op(B) = B[K,N] (transB=0) or B[N,K]^T (transB=1)
// CTA tile 128x64, 8 warps (4m x 2n), warp tile 32x32, BK=16.
__global__ void __launch_bounds__(256, 2) k_mma_gemm(
    const float* __restrict__ A, const float* __restrict__ B,
    const float* __restrict__ bias, const float* __restrict__ Add,
    float* __restrict__ C,
    int K, int lda, int ldb, int ldc, int ldadd, int zdiv,
    long long sA1, long long sA0, long long sB1, long long sB0,
    long long sC1, long long sC0, long long sAdd1, long long sAdd0,
    float alpha, float addScale, int transB)
{
    __shared__ float sm[SMEM_FLOATS];

    const int tid = threadIdx.x;
    const int wid = tid >> 5;
    const int lane = tid & 31;

    const int z = blockIdx.z;
    const int z1 = z / zdiv, z0 = z % zdiv;
    A += z1 * sA1 + z0 * sA0;
    B += z1 * sB1 + z0 * sB0;
    C += z1 * sC1 + z0 * sC0;
    if (Add) Add += z1 * sAdd1 + z0 * sAdd0;

    const int m0 = blockIdx.y * 128;
    const int n0 = blockIdx.x * 64;

    const int wm0 = (wid >> 1) * 32;   // warp row origin
    const int wn0 = (wid & 1) * 32;    // warp col origin

    // global-load coords
    const int ar = tid >> 1, ahalf = tid & 1;   // A: 128 rows x 2 chunks of 8
    const int nkr = tid >> 4, nnc = (tid & 15) * 4;  // B NN: 16 k-rows x 4-float chunks
    const int ntr = tid >> 2, ntk = (tid & 3) * 4;   // B NT: 64 n-rows x 4-float chunks

    const int fg = lane >> 2;   // fragment group (0..7)
    const int ft = lane & 3;    // thread-in-group

    float acc[2][4][4];
    #pragma unroll
    for (int i = 0; i < 2; ++i)
        #pragma unroll
        for (int j = 0; j < 4; ++j)
            #pragma unroll
            for (int e = 0; e < 4; ++e) acc[i][j][e] = 0.0f;

    const int nIter = K >> 4;   // BK = 16
    for (int it = 0; it < nIter; ++it) {
        const int k0 = it << 4;
        __syncthreads();

        // ---- A tile: 128x16 fp32 -> hi/lo tf32
        {
            const float* src = A + (long long)(m0 + ar) * lda + k0 + ahalf * 8;
            float f[8];
            *(float4*)(f)     = *(const float4*)(src);
            *(float4*)(f + 4) = *(const float4*)(src + 4);
            float hi[8], lo[8];
            #pragma unroll
            for (int e = 0; e < 8; ++e) {
                hi[e] = to_tf32(f[e]);
                lo[e] = to_tf32(f[e] - hi[e]);
            }
            const int base = ar * A_ST + ahalf * 8;
            *(float4*)(sm + SA_HI + base)     = *(float4*)(hi);
            *(float4*)(sm + SA_HI + base + 4) = *(float4*)(hi + 4);
            *(float4*)(sm + SA_LO + base)     = *(float4*)(lo);
            *(float4*)(sm + SA_LO + base + 4) = *(float4*)(lo + 4);
        }
        // ---- B tile -> smem [k][n]
        if (transB) {   // B[N,K]: load 4 k-floats for one n, scatter-transpose
            const float* src = B + (long long)(n0 + ntr) * ldb + k0 + ntk;
            float4 f4 = *(const float4*)(src);
            const float fv[4] = {f4.x, f4.y, f4.z, f4.w};
            #pragma unroll
            for (int e = 0; e < 4; ++e) {
                float hi = to_tf32(fv[e]);
                float lo = to_tf32(fv[e] - hi);
                sm[SB_HI + (ntk + e) * B_ST + ntr] = hi;
                sm[SB_LO + (ntk + e) * B_ST + ntr] = lo;
            }
        } else {        // B[K,N]: direct rows
            const float* src = B + (long long)(k0 + nkr) * ldb + n0 + nnc;
            float4 f4 = *(const float4*)(src);
            float hi[4], lo[4];
            const float fv[4] = {f4.x, f4.y, f4.z, f4.w};
            #pragma unroll
            for (int e = 0; e < 4; ++e) {
                hi[e] = to_tf32(fv[e]);
                lo[e] = to_tf32(fv[e] - hi[e]);
            }
            const int base = nkr * B_ST + nnc;
            *(float4*)(sm + SB_HI + base) = *(float4*)(hi);
            *(float4*)(sm + SB_LO + base) = *(float4*)(lo);
        }
        __syncthreads();

        // ---- compute: 2 k8 steps
        #pragma unroll
        for (int ks = 0; ks < 2; ++ks) {
            const int kb = ks * 8;

            float ahi[2][4], alo[2][4];
            #pragma unroll
            for (int mi = 0; mi < 2; ++mi) {
                const int r = wm0 + mi * 16 + fg;
                const int c = kb + ft;
                ahi[mi][0] = sm[SA_HI + r * A_ST + c];
                ahi[mi][1] = sm[SA_HI + (r + 8) * A_ST + c];
                ahi[mi][2] = sm[SA_HI + r * A_ST + c + 4];
                ahi[mi][3] = sm[SA_HI + (r + 8) * A_ST + c + 4];
                alo[mi][0] = sm[SA_LO + r * A_ST + c];
                alo[mi][1] = sm[SA_LO + (r + 8) * A_ST + c];
                alo[mi][2] = sm[SA_LO + r * A_ST + c + 4];
                alo[mi][3] = sm[SA_LO + (r + 8) * A_ST + c + 4];
            }
            float bhi[4][2], blo[4][2];
            #pragma unroll
            for (int nj = 0; nj < 4; ++nj) {
                const int n = wn0 + nj * 8 + fg;
                const int kk = kb + ft;
                bhi[nj][0] = sm[SB_HI + kk * B_ST + n];
                bhi[nj][1] = sm[SB_HI + (kk + 4) * B_ST + n];
                blo[nj][0] = sm[SB_LO + kk * B_ST + n];
                blo[nj][1] = sm[SB_LO + (kk + 4) * B_ST + n];
            }
            #pragma unroll
            for (int mi = 0; mi < 2; ++mi)
                #pragma unroll
                for (int nj = 0; nj < 4; ++nj) {
                    mma_tf32(acc[mi][nj], ahi[mi], bhi[nj]);
                    mma_tf32(acc[mi][nj], ahi[mi], blo[nj]);
                    mma_tf32(acc[mi][nj], alo[mi], bhi[nj]);
                }
        }
    }

    // ---- epilogue: fragment -> global (float2 stores)
    #pragma unroll
    for (int mi = 0; mi < 2; ++mi) {
        #pragma unroll
        for (int jj = 0; jj < 4; ++jj) {
            const long long r0 = m0 + wm0 + mi * 16 + fg;
            const long long r1 = r0 + 8;
            const int col = n0 + wn0 + jj * 8 + ft * 2;
            float v00 = acc[mi][jj][0] * alpha, v01 = acc[mi][jj][1] * alpha;
            float v10 = acc[mi][jj][2] * alpha, v11 = acc[mi][jj][3] * alpha;
            if (bias) { v00 += bias[col]; v01 += bias[col + 1];
                        v10 += bias[col]; v11 += bias[col + 1]; }
            if (Add) {
                v00 += addScale * Add[r0 * ldadd + col];
                v01 += addScale * Add[r0 * ldadd + col + 1];
                v10 += addScale * Add[r1 * ldadd + col];
                v11 += addScale * Add[r1 * ldadd + col + 1];
            }
            *(float2*)&C[r0 * ldc + col] = make_float2(v00, v01);
            *(float2*)&C[r1 * ldc + col] = make_float2(v10, v11);
        }
    }
}

// ---------------- softmax over 2048 cols, one block per row ----------------
__global__ void __launch_bounds__(256) k_softmax2048(float* __restrict__ X)
{
    long long row = blockIdx.x;
    float* x = X + row * 2048;
    int tid = threadIdx.x;
    __shared__ float red[256];

    float v[8];
    float m = -1e30f;
    #pragma unroll
    for (int i = 0; i < 8; ++i) { v[i] = x[tid + i * 256]; m = fmaxf(m, v[i]); }
    red[tid] = m; __syncthreads();
    for (int s = 128; s > 0; s >>= 1) {
        if (tid < s) red[tid] = fmaxf(red[tid], red[tid + s]);
        __syncthreads();
    }
    m = red[0]; __syncthreads();

    float sum = 0.0f;
    #pragma unroll
    for (int i = 0; i < 8; ++i) { v[i] = __expf(v[i] - m); sum += v[i]; }
    red[tid] = sum; __syncthreads();
    for (int s = 128; s > 0; s >>= 1) {
        if (tid < s) red[tid] += red[tid + s];
        __syncthreads();
    }
    float inv = 1.0f / red[0];
    #pragma unroll
    for (int i = 0; i < 8; ++i) x[tid + i * 256] = v[i] * inv;
}

// ---------------- residual + LayerNorm ----------------
__global__ void __launch_bounds__(256) k_ln_res(
    const float* __restrict__ xin, const float* __restrict__ hs,
    const float* __restrict__ g, const float* __restrict__ be,
    float* __restrict__ out)
{
    long long row = blockIdx.x;
    const float* xr = xin + row * H_;
    const float* hr = hs + row * H_;
    float* orow = out + row * H_;
    int tid = threadIdx.x;
    __shared__ float red[256];

    float v[4];
    float s = 0.0f;
    #pragma unroll
    for (int i = 0; i < 4; ++i) { v[i] = xr[tid + i * 256] + hr[tid + i * 256]; s += v[i]; }
    red[tid] = s; __syncthreads();
    for (int t = 128; t > 0; t >>= 1) {
        if (tid < t) red[tid] += red[tid + t];
        __syncthreads();
    }
    float mu = red[0] * (1.0f / H_); __syncthreads();

    float var = 0.0f;
    #pragma unroll
    for (int i = 0; i < 4; ++i) { float d = v[i] - mu; var += d * d; }
    red[tid] = var; __syncthreads();
    for (int t = 128; t > 0; t >>= 1) {
        if (tid < t) red[tid] += red[tid + t];
        __syncthreads();
    }
    float inv = rsqrtf(red[0] * (1.0f / H_) + 1e-12f);
    #pragma unroll
    for (int i = 0; i < 4; ++i) {
        int c = tid + i * 256;
        orow[c] = (v[i] - mu) * inv * g[c] + be[c];
    }
}

// ---------------- host-side launch helper ----------------
static void launch_gemm(
    const float* A, const float* B, const float* bias, const float* Add, float* C,
    int Mrows, int Ncols, int K, int lda, int ldb, int ldc, int ldadd,
    int Z, int zdiv,
    long long sA1, long long sA0, long long sB1, long long sB0,
    long long sC1, long long sC0, long long sAdd1, long long sAdd0,
    float alpha, float addScale, int transB)
{
    dim3 grid(Ncols / 64, Mrows / 128, Z);
    k_mma_gemm<<<grid, 256>>>(
        A, B, bias, Add, C, K, lda, ldb, ldc, ldadd, zdiv,
        sA1, sA0, sB1, sB0, sC1, sC0, sAdd1, sAdd0,
        alpha, addScale, transB);
}

extern "C" void kernel_launch(void* const* d_in, const int* in_sizes, int n_in,
                              void* d_out, int out_size)
{
    const float* hs  = (const float*)d_in[0];
    const float* mc  = (const float*)d_in[1];
    const float* Wq  = (const float*)d_in[2];  const float* bq  = (const float*)d_in[3];
    const float* Wk  = (const float*)d_in[4];  const float* bk  = (const float*)d_in[5];
    const float* Wv  = (const float*)d_in[6];  const float* bv  = (const float*)d_in[7];
    const float* Wmq = (const float*)d_in[8];  const float* bmq = (const float*)d_in[9];
    const float* Wmk = (const float*)d_in[10]; const float* bmk = (const float*)d_in[11];
    const float* Wc  = (const float*)d_in[12]; const float* bc  = (const float*)d_in[13];
    const float* Wf  = (const float*)d_in[14]; const float* bf  = (const float*)d_in[15];
    const float* lg  = (const float*)d_in[16]; const float* lb  = (const float*)d_in[17];

    float* out   = (float*)d_out;                        // [B,S,H]
    float* probs = out + (long long)B_ * S_ * H_;        // [B,NH,S,S]

    float *q, *k, *v, *mq, *mk, *med, *cat, *x;
    cudaGetSymbolAddress((void**)&q,   g_q);
    cudaGetSymbolAddress((void**)&k,   g_k);
    cudaGetSymbolAddress((void**)&v,   g_v);
    cudaGetSymbolAddress((void**)&mq,  g_mq);
    cudaGetSymbolAddress((void**)&mk,  g_mk);
    cudaGetSymbolAddress((void**)&med, g_med);
    cudaGetSymbolAddress((void**)&cat, g_cat);
    cudaGetSymbolAddress((void**)&x,   g_x);

    const int rows = B_ * S_;            // 4096
    const long long SS = (long long)S_ * S_;
    const long long SH = (long long)S_ * H_;
    const long long SM = (long long)S_ * M_;

    // Q, K, V projections [4096,1024] @ [1024,1024] + bias  (NN)
    launch_gemm(hs, Wq, bq, nullptr, q, rows, H_, H_, H_, H_, H_, 0, 1, 1,
                0,0, 0,0, 0,0, 0,0, 1.0f, 0.0f, 0);
    launch_gemm(hs, Wk, bk, nullptr, k, rows, H_, H_, H_, H_, H_, 0, 1, 1,
                0,0, 0,0, 0,0, 0,0, 1.0f, 0.0f, 0);
    launch_gemm(hs, Wv, bv, nullptr, v, rows, H_, H_, H_, H_, H_, 0, 1, 1,
                0,0, 0,0, 0,0, 0,0, 1.0f, 0.0f, 0);

    // medical projections [4096,1024] @ [1024,512] + bias  (NN)
    launch_gemm(hs, Wmq, bmq, nullptr, mq, rows, M_, H_, H_, M_, M_, 0, 1, 1,
                0,0, 0,0, 0,0, 0,0, 1.0f, 0.0f, 0);
    launch_gemm(mc, Wmk, bmk, nullptr, mk, rows, M_, H_, H_, M_, M_, 0, 1, 1,
                0,0, 0,0, 0,0, 0,0, 1.0f, 0.0f, 0);

    // med scores: per-batch mq @ mk^T [2048,512] x [2048,512]^T -> [2048,2048] (NT)
    // zdiv=1 -> z1 = z = batch index, so batch strides go in the s*1 slots.
    launch_gemm(mq, mk, nullptr, nullptr, med, S_, S_, M_, M_, M_, S_, 0, B_, 1,
                SM, 0, SM, 0, SS, 0, 0, 0, 1.0f, 0.0f, 1);
    k_softmax2048<<<B_ * S_, 256>>>(med);

    // attention scores: q@k^T/8 + 0.3*med -> probs  (NT, per b,h)
    launch_gemm(q, k, nullptr, med, probs, S_, S_, D_, H_, H_, S_, S_,
                B_ * NH_, NH_,
                SH, D_, SH, D_, NH_ * SS, SS, SS, 0,
                0.125f, 0.3f, 1);
    k_softmax2048<<<B_ * NH_ * S_, 256>>>(probs);

    // ctx = probs @ v -> cat[:, 0:1024]  (NN, per b,h)
    launch_gemm(probs, v, nullptr, nullptr, cat, S_, D_, S_, S_, H_, CAT_, 0,
                B_ * NH_, NH_,
                NH_ * SS, SS, SH, D_, (long long)S_ * CAT_, D_, 0, 0,
                1.0f, 0.0f, 0);

    // clin = ctx @ Wc + bc -> cat[:, 1024:1536]  (NN)
    launch_gemm(cat, Wc, bc, nullptr, cat + H_, rows, M_, H_, CAT_, M_, CAT_, 0, 1, 1,
                0,0, 0,0, 0,0, 0,0, 1.0f, 0.0f, 0);

    // final = cat @ Wf + bf  [4096,1536] @ [1536,1024]  (NN)
    launch_gemm(cat, Wf, bf, nullptr, x, rows, H_, CAT_, CAT_, H_, H_, 0, 1, 1,
                0,0, 0,0, 0,0, 0,0, 1.0f, 0.0f, 0);

    // residual + layernorm -> out
    k_ln_res<<<rows, 256>>>(x, hs, lg, lb, out);
}

// round 6
// speedup vs baseline: 2.5296x; 1.5468x over previous
#include <cuda_runtime.h>
#include <cuda_bf16.h>
#include <cstdint>

// Shapes (fixed by the problem)
#define B_   2
#define S_   2048
#define H_   1024
#define NH_  16
#define M_   512
#define D_   64
#define CAT_ (H_ + M_)   // 1536

// ---------------- scratch (static device memory; no allocations allowed) ---
__device__ float g_q  [(long long)B_*S_*H_];
__device__ float g_k  [(long long)B_*S_*H_];
__device__ float g_v  [(long long)B_*S_*H_];
__device__ float g_mq [(long long)B_*S_*M_];
__device__ float g_mk [(long long)B_*S_*M_];
__device__ float g_med[(long long)B_*S_*S_];
__device__ float g_cat[(long long)B_*S_*CAT_];
__device__ float g_x  [(long long)B_*S_*H_];

// ---------------- helpers ----------------
__device__ __forceinline__ uint32_t smem_to_u32(const void* p) {
    uint32_t a;
    asm("{ .reg .u64 t; cvta.to.shared.u64 t, %1; cvt.u32.u64 %0, t; }" : "=r"(a) : "l"(p));
    return a;
}
__device__ __forceinline__ void ldmx4(uint32_t* r, uint32_t addr) {
    asm volatile("ldmatrix.sync.aligned.m8n8.x4.shared.b16 {%0,%1,%2,%3}, [%4];"
        : "=r"(r[0]), "=r"(r[1]), "=r"(r[2]), "=r"(r[3]) : "r"(addr));
}
__device__ __forceinline__ void ldmx4t(uint32_t* r, uint32_t addr) {
    asm volatile("ldmatrix.sync.aligned.m8n8.x4.trans.shared.b16 {%0,%1,%2,%3}, [%4];"
        : "=r"(r[0]), "=r"(r[1]), "=r"(r[2]), "=r"(r[3]) : "r"(addr));
}
__device__ __forceinline__ void mma16816(float* d, const uint32_t* a, const uint32_t* b) {
    asm volatile(
        "mma.sync.aligned.m16n8k16.row.col.f32.bf16.bf16.f32 "
        "{%0,%1,%2,%3}, {%4,%5,%6,%7}, {%8,%9}, {%0,%1,%2,%3};"
        : "+f"(d[0]), "+f"(d[1]), "+f"(d[2]), "+f"(d[3])
        : "r"(a[0]), "r"(a[1]), "r"(a[2]), "r"(a[3]), "r"(b[0]), "r"(b[1]));
}

struct alignas(16) BF8 { __nv_bfloat16 v[8]; };
__device__ __forceinline__ void split8(const float* f, BF8& hi, BF8& lo) {
    #pragma unroll
    for (int i = 0; i < 8; ++i) {
        __nv_bfloat16 h = __float2bfloat16(f[i]);
        hi.v[i] = h;
        lo.v[i] = __float2bfloat16(f[i] - __bfloat162float(h));
    }
}

// ---------------- smem layout ----------------
// A tiles: [128 rows][32 bf16] padded to 40 elems (80B stride)  -> 10240 B each
// B tiles: NT [64][32] pad 40 (80B)  = 5120 B ; NN [32][64] pad 72 (144B) = 4608 B
#define A_STRIDE_B 80
#define BNT_STRIDE_B 80
#define BNN_STRIDE_B 144
#define OFF_AHI 0
#define OFF_ALO 10240
#define OFF_BHI 20480
#define OFF_BLO 25600
#define SMEM_TOTAL 30720

// ---------------- universal bf16-split mma.sync GEMM ----------------
// C[M,N] = alpha * A[M,K] @ op(B) (+bias[col]) (+addScale*Add[row,col])
// op(B) = B[K,N] (transB=0) or B[N,K]^T (transB=1)
__global__ void __launch_bounds__(256, 2) k_mma_gemm(
    const float* __restrict__ A, const float* __restrict__ B,
    const float* __restrict__ bias, const float* __restrict__ Add,
    float* __restrict__ C,
    int K, int lda, int ldb, int ldc, int ldadd, int zdiv,
    long long sA1, long long sA0, long long sB1, long long sB0,
    long long sC1, long long sC0, long long sAdd1, long long sAdd0,
    float alpha, float addScale, int transB)
{
    __shared__ __align__(16) uint8_t smem[SMEM_TOTAL];
    const uint32_t sb = smem_to_u32(smem);

    const int tid = threadIdx.x;
    const int wid = tid >> 5;
    const int lane = tid & 31;

    const int z = blockIdx.z;
    const int z1 = z / zdiv, z0 = z % zdiv;
    A += z1 * sA1 + z0 * sA0;
    B += z1 * sB1 + z0 * sB0;
    C += z1 * sC1 + z0 * sC0;
    if (Add) Add += z1 * sAdd1 + z0 * sAdd0;

    const int m0 = blockIdx.y * 128;
    const int n0 = blockIdx.x * 64;

    const int wm0 = (wid >> 1) * 32;   // warp row origin in CTA tile
    const int wn0 = (wid & 1) * 32;    // warp col origin

    // ldmatrix per-lane address components (byte offsets inside a tile buffer)
    // A (non-trans): rows (lane&15), k-half (lane>>4)*8
    const uint32_t aLane = (uint32_t)(wm0 + (lane & 15)) * A_STRIDE_B + ((lane >> 4) << 3) * 2;
    // B NT (non-trans) on [N][K]: n row = wn0 + ((lane>>1)&8) + (lane&7), k half = lane&8
    const uint32_t bLaneNT = (uint32_t)(wn0 + ((lane >> 1) & 8) + (lane & 7)) * BNT_STRIDE_B
                           + (uint32_t)(lane & 8) * 2;
    // B NN (trans) on [K][N]: k row = lane&15, n col = wn0 + ((lane>>1)&8)
    const uint32_t bLaneNN = (uint32_t)(lane & 15) * BNN_STRIDE_B
                           + (uint32_t)(wn0 + ((lane >> 1) & 8)) * 2;

    // global-load coords
    const int ar = tid >> 1, ahalf = tid & 1;          // A: 128 rows x 2 halves(16 floats)
    const int ntr = tid >> 2, ntq = tid & 3;           // B NT: 64 rows x 4 chunks(8 floats)
    const int nnr = tid >> 3, nnc = tid & 7;           // B NN: 32 rows x 8 chunks(8 floats)

    float acc[2][4][4];
    #pragma unroll
    for (int i = 0; i < 2; ++i)
        #pragma unroll
        for (int j = 0; j < 4; ++j)
            #pragma unroll
            for (int e = 0; e < 4; ++e) acc[i][j][e] = 0.0f;

    const int nIter = K >> 5;   // BK = 32
    for (int it = 0; it < nIter; ++it) {
        const int k0 = it << 5;
        __syncthreads();

        // ---- A tile: 128x32 fp32 -> hi/lo bf16
        {
            const float* src = A + (long long)(m0 + ar) * lda + k0 + ahalf * 16;
            float f[16];
            *(float4*)(f)      = *(const float4*)(src);
            *(float4*)(f + 4)  = *(const float4*)(src + 4);
            *(float4*)(f + 8)  = *(const float4*)(src + 8);
            *(float4*)(f + 12) = *(const float4*)(src + 12);
            BF8 h0, l0, h1, l1;
            split8(f, h0, l0); split8(f + 8, h1, l1);
            const uint32_t off = (uint32_t)ar * A_STRIDE_B + ahalf * 32;
            *(uint4*)(smem + OFF_AHI + off)      = *(const uint4*)&h0;
            *(uint4*)(smem + OFF_AHI + off + 16) = *(const uint4*)&h1;
            *(uint4*)(smem + OFF_ALO + off)      = *(const uint4*)&l0;
            *(uint4*)(smem + OFF_ALO + off + 16) = *(const uint4*)&l1;
        }
        // ---- B tile
        if (transB) {   // B[N,K] row-major -> Bs[n][k], direct
            const float* src = B + (long long)(n0 + ntr) * ldb + k0 + ntq * 8;
            float f[8];
            *(float4*)(f)     = *(const float4*)(src);
            *(float4*)(f + 4) = *(const float4*)(src + 4);
            BF8 h, l; split8(f, h, l);
            const uint32_t off = (uint32_t)ntr * BNT_STRIDE_B + ntq * 16;
            *(uint4*)(smem + OFF_BHI + off) = *(const uint4*)&h;
            *(uint4*)(smem + OFF_BLO + off) = *(const uint4*)&l;
        } else {        // B[K,N] row-major -> Bs[k][n], direct
            const float* src = B + (long long)(k0 + nnr) * ldb + n0 + nnc * 8;
            float f[8];
            *(float4*)(f)     = *(const float4*)(src);
            *(float4*)(f + 4) = *(const float4*)(src + 4);
            BF8 h, l; split8(f, h, l);
            const uint32_t off = (uint32_t)nnr * BNN_STRIDE_B + nnc * 16;
            *(uint4*)(smem + OFF_BHI + off) = *(const uint4*)&h;
            *(uint4*)(smem + OFF_BLO + off) = *(const uint4*)&l;
        }
        __syncthreads();

        // ---- compute: 2 k16 steps
        #pragma unroll
        for (int kk = 0; kk < 2; ++kk) {
            uint32_t ahi[2][4], alo[2][4], bhi[2][4], blo[2][4];
            const uint32_t akk = aLane + (uint32_t)(kk * 16) * 2;
            #pragma unroll
            for (int mi = 0; mi < 2; ++mi) {
                const uint32_t off = akk + (uint32_t)(mi * 16) * A_STRIDE_B;
                ldmx4(ahi[mi], sb + OFF_AHI + off);
                ldmx4(alo[mi], sb + OFF_ALO + off);
            }
            if (transB) {
                const uint32_t bkk = bLaneNT + (uint32_t)(kk * 16) * 2;
                #pragma unroll
                for (int nj = 0; nj < 2; ++nj) {
                    const uint32_t off = bkk + (uint32_t)(nj * 16) * BNT_STRIDE_B;
                    ldmx4(bhi[nj], sb + OFF_BHI + off);
                    ldmx4(blo[nj], sb + OFF_BLO + off);
                }
            } else {
                const uint32_t bkk = bLaneNN + (uint32_t)(kk * 16) * BNN_STRIDE_B;
                #pragma unroll
                for (int nj = 0; nj < 2; ++nj) {
                    const uint32_t off = bkk + (uint32_t)(nj * 16) * 2;
                    ldmx4t(bhi[nj], sb + OFF_BHI + off);
                    ldmx4t(blo[nj], sb + OFF_BLO + off);
                }
            }
            #pragma unroll
            for (int mi = 0; mi < 2; ++mi)
                #pragma unroll
                for (int jj = 0; jj < 4; ++jj) {
                    const uint32_t* bh = &bhi[jj >> 1][(jj & 1) * 2];
                    const uint32_t* bl = &blo[jj >> 1][(jj & 1) * 2];
                    mma16816(acc[mi][jj], ahi[mi], bh);
                    mma16816(acc[mi][jj], ahi[mi], bl);
                    mma16816(acc[mi][jj], alo[mi], bh);
                }
        }
    }

    // ---- epilogue: fragment -> global (float2 stores)
    const int g = lane >> 2, t = lane & 3;
    #pragma unroll
    for (int mi = 0; mi < 2; ++mi) {
        #pragma unroll
        for (int jj = 0; jj < 4; ++jj) {
            const long long r0 = m0 + wm0 + mi * 16 + g;
            const long long r1 = r0 + 8;
            const int col = n0 + wn0 + jj * 8 + t * 2;
            float v00 = acc[mi][jj][0] * alpha, v01 = acc[mi][jj][1] * alpha;
            float v10 = acc[mi][jj][2] * alpha, v11 = acc[mi][jj][3] * alpha;
            if (bias) { v00 += bias[col]; v01 += bias[col + 1];
                        v10 += bias[col]; v11 += bias[col + 1]; }
            if (Add) {
                v00 += addScale * Add[r0 * ldadd + col];
                v01 += addScale * Add[r0 * ldadd + col + 1];
                v10 += addScale * Add[r1 * ldadd + col];
                v11 += addScale * Add[r1 * ldadd + col + 1];
            }
            *(float2*)&C[r0 * ldc + col] = make_float2(v00, v01);
            *(float2*)&C[r1 * ldc + col] = make_float2(v10, v11);
        }
    }
}

// ---------------- softmax over 2048 cols, one block per row ----------------
__global__ void __launch_bounds__(256) k_softmax2048(float* __restrict__ X)
{
    long long row = blockIdx.x;
    float* x = X + row * 2048;
    int tid = threadIdx.x;
    __shared__ float red[256];

    float v[8];
    float m = -1e30f;
    #pragma unroll
    for (int i = 0; i < 8; ++i) { v[i] = x[tid + i * 256]; m = fmaxf(m, v[i]); }
    red[tid] = m; __syncthreads();
    for (int s = 128; s > 0; s >>= 1) {
        if (tid < s) red[tid] = fmaxf(red[tid], red[tid + s]);
        __syncthreads();
    }
    m = red[0]; __syncthreads();

    float sum = 0.0f;
    #pragma unroll
    for (int i = 0; i < 8; ++i) { v[i] = __expf(v[i] - m); sum += v[i]; }
    red[tid] = sum; __syncthreads();
    for (int s = 128; s > 0; s >>= 1) {
        if (tid < s) red[tid] += red[tid + s];
        __syncthreads();
    }
    float inv = 1.0f / red[0];
    #pragma unroll
    for (int i = 0; i < 8; ++i) x[tid + i * 256] = v[i] * inv;
}

// ---------------- residual + LayerNorm ----------------
__global__ void __launch_bounds__(256) k_ln_res(
    const float* __restrict__ xin, const float* __restrict__ hs,
    const float* __restrict__ g, const float* __restrict__ be,
    float* __restrict__ out)
{
    long long row = blockIdx.x;
    const float* xr = xin + row * H_;
    const float* hr = hs + row * H_;
    float* orow = out + row * H_;
    int tid = threadIdx.x;
    __shared__ float red[256];

    float v[4];
    float s = 0.0f;
    #pragma unroll
    for (int i = 0; i < 4; ++i) { v[i] = xr[tid + i * 256] + hr[tid + i * 256]; s += v[i]; }
    red[tid] = s; __syncthreads();
    for (int t = 128; t > 0; t >>= 1) {
        if (tid < t) red[tid] += red[tid + t];
        __syncthreads();
    }
    float mu = red[0] * (1.0f / H_); __syncthreads();

    float var = 0.0f;
    #pragma unroll
    for (int i = 0; i < 4; ++i) { float d = v[i] - mu; var += d * d; }
    red[tid] = var; __syncthreads();
    for (int t = 128; t > 0; t >>= 1) {
        if (tid < t) red[tid] += red[tid + t];
        __syncthreads();
    }
    float inv = rsqrtf(red[0] * (1.0f / H_) + 1e-12f);
    #pragma unroll
    for (int i = 0; i < 4; ++i) {
        int c = tid + i * 256;
        orow[c] = (v[i] - mu) * inv * g[c] + be[c];
    }
}

// ---------------- host-side launch helper ----------------
static void launch_gemm(
    const float* A, const float* B, const float* bias, const float* Add, float* C,
    int Mrows, int Ncols, int K, int lda, int ldb, int ldc, int ldadd,
    int Z, int zdiv,
    long long sA1, long long sA0, long long sB1, long long sB0,
    long long sC1, long long sC0, long long sAdd1, long long sAdd0,
    float alpha, float addScale, int transB)
{
    dim3 grid(Ncols / 64, Mrows / 128, Z);
    k_mma_gemm<<<grid, 256>>>(
        A, B, bias, Add, C, K, lda, ldb, ldc, ldadd, zdiv,
        sA1, sA0, sB1, sB0, sC1, sC0, sAdd1, sAdd0,
        alpha, addScale, transB);
}

extern "C" void kernel_launch(void* const* d_in, const int* in_sizes, int n_in,
                              void* d_out, int out_size)
{
    const float* hs  = (const float*)d_in[0];
    const float* mc  = (const float*)d_in[1];
    const float* Wq  = (const float*)d_in[2];  const float* bq  = (const float*)d_in[3];
    const float* Wk  = (const float*)d_in[4];  const float* bk  = (const float*)d_in[5];
    const float* Wv  = (const float*)d_in[6];  const float* bv  = (const float*)d_in[7];
    const float* Wmq = (const float*)d_in[8];  const float* bmq = (const float*)d_in[9];
    const float* Wmk = (const float*)d_in[10]; const float* bmk = (const float*)d_in[11];
    const float* Wc  = (const float*)d_in[12]; const float* bc  = (const float*)d_in[13];
    const float* Wf  = (const float*)d_in[14]; const float* bf  = (const float*)d_in[15];
    const float* lg  = (const float*)d_in[16]; const float* lb  = (const float*)d_in[17];

    float* out   = (float*)d_out;                        // [B,S,H]
    float* probs = out + (long long)B_ * S_ * H_;        // [B,NH,S,S]

    float *q, *k, *v, *mq, *mk, *med, *cat, *x;
    cudaGetSymbolAddress((void**)&q,   g_q);
    cudaGetSymbolAddress((void**)&k,   g_k);
    cudaGetSymbolAddress((void**)&v,   g_v);
    cudaGetSymbolAddress((void**)&mq,  g_mq);
    cudaGetSymbolAddress((void**)&mk,  g_mk);
    cudaGetSymbolAddress((void**)&med, g_med);
    cudaGetSymbolAddress((void**)&cat, g_cat);
    cudaGetSymbolAddress((void**)&x,   g_x);

    const int rows = B_ * S_;            // 4096
    const long long SS = (long long)S_ * S_;
    const long long SH = (long long)S_ * H_;
    const long long SM = (long long)S_ * M_;

    // Q, K, V projections [4096,1024] @ [1024,1024] + bias  (NN)
    launch_gemm(hs, Wq, bq, nullptr, q, rows, H_, H_, H_, H_, H_, 0, 1, 1,
                0,0, 0,0, 0,0, 0,0, 1.0f, 0.0f, 0);
    launch_gemm(hs, Wk, bk, nullptr, k, rows, H_, H_, H_, H_, H_, 0, 1, 1,
                0,0, 0,0, 0,0, 0,0, 1.0f, 0.0f, 0);
    launch_gemm(hs, Wv, bv, nullptr, v, rows, H_, H_, H_, H_, H_, 0, 1, 1,
                0,0, 0,0, 0,0, 0,0, 1.0f, 0.0f, 0);

    // medical projections [4096,1024] @ [1024,512] + bias  (NN)
    launch_gemm(hs, Wmq, bmq, nullptr, mq, rows, M_, H_, H_, M_, M_, 0, 1, 1,
                0,0, 0,0, 0,0, 0,0, 1.0f, 0.0f, 0);
    launch_gemm(mc, Wmk, bmk, nullptr, mk, rows, M_, H_, H_, M_, M_, 0, 1, 1,
                0,0, 0,0, 0,0, 0,0, 1.0f, 0.0f, 0);

    // med scores: per-batch mq @ mk^T [2048,512] x [2048,512]^T -> [2048,2048] (NT)
    // zdiv=1 -> z1 = z = batch index, so batch strides go in the s*1 slots.
    launch_gemm(mq, mk, nullptr, nullptr, med, S_, S_, M_, M_, M_, S_, 0, B_, 1,
                SM, 0, SM, 0, SS, 0, 0, 0, 1.0f, 0.0f, 1);
    k_softmax2048<<<B_ * S_, 256>>>(med);

    // attention scores: q@k^T/8 + 0.3*med -> probs  (NT, per b,h)
    launch_gemm(q, k, nullptr, med, probs, S_, S_, D_, H_, H_, S_, S_,
                B_ * NH_, NH_,
                SH, D_, SH, D_, NH_ * SS, SS, SS, 0,
                0.125f, 0.3f, 1);
    k_softmax2048<<<B_ * NH_ * S_, 256>>>(probs);

    // ctx = probs @ v -> cat[:, 0:1024]  (NN, per b,h)
    launch_gemm(probs, v, nullptr, nullptr, cat, S_, D_, S_, S_, H_, CAT_, 0,
                B_ * NH_, NH_,
                NH_ * SS, SS, SH, D_, (long long)S_ * CAT_, D_, 0, 0,
                1.0f, 0.0f, 0);

    // clin = ctx @ Wc + bc -> cat[:, 1024:1536]  (NN)
    launch_gemm(cat, Wc, bc, nullptr, cat + H_, rows, M_, H_, CAT_, M_, CAT_, 0, 1, 1,
                0,0, 0,0, 0,0, 0,0, 1.0f, 0.0f, 0);

    // final = cat @ Wf + bf  [4096,1536] @ [1536,1024]  (NN)
    launch_gemm(cat, Wf, bf, nullptr, x, rows, H_, CAT_, CAT_, H_, H_, 0, 1, 1,
                0,0, 0,0, 0,0, 0,0, 1.0f, 0.0f, 0);

    // residual + layernorm -> out
    k_ln_res<<<rows, 256>>>(x, hs, lg, lb, out);
}

// round 7
// speedup vs baseline: 2.7524x; 1.0881x over previous
#include <cuda_runtime.h>
#include <cuda_bf16.h>
#include <cstdint>

// Shapes (fixed by the problem)
#define B_   2
#define S_   2048
#define H_   1024
#define NH_  16
#define M_   512
#define D_   64
#define CAT_ (H_ + M_)   // 1536

// ---------------- scratch (static device memory; no allocations allowed) ---
__device__ float g_q  [(long long)B_*S_*H_];
__device__ float g_k  [(long long)B_*S_*H_];
__device__ float g_v  [(long long)B_*S_*H_];
__device__ float g_mq [(long long)B_*S_*M_];
__device__ float g_mk [(long long)B_*S_*M_];
__device__ float g_med[(long long)B_*S_*S_];
__device__ float g_cat[(long long)B_*S_*CAT_];
__device__ float g_x  [(long long)B_*S_*H_];
__device__ float g_part[(long long)B_*NH_*S_*32];   // per-tile row partial sums
__device__ float g_minv[(long long)B_*S_];          // med row inv sums
__device__ float g_pinv[(long long)B_*NH_*S_];      // probs row inv sums

// ---------------- helpers ----------------
__device__ __forceinline__ uint32_t smem_to_u32(const void* p) {
    uint32_t a;
    asm("{ .reg .u64 t; cvta.to.shared.u64 t, %1; cvt.u32.u64 %0, t; }" : "=r"(a) : "l"(p));
    return a;
}
__device__ __forceinline__ void ldmx4(uint32_t* r, uint32_t addr) {
    asm volatile("ldmatrix.sync.aligned.m8n8.x4.shared.b16 {%0,%1,%2,%3}, [%4];"
        : "=r"(r[0]), "=r"(r[1]), "=r"(r[2]), "=r"(r[3]) : "r"(addr));
}
__device__ __forceinline__ void ldmx4t(uint32_t* r, uint32_t addr) {
    asm volatile("ldmatrix.sync.aligned.m8n8.x4.trans.shared.b16 {%0,%1,%2,%3}, [%4];"
        : "=r"(r[0]), "=r"(r[1]), "=r"(r[2]), "=r"(r[3]) : "r"(addr));
}
__device__ __forceinline__ void mma16816(float* d, const uint32_t* a, const uint32_t* b) {
    asm volatile(
        "mma.sync.aligned.m16n8k16.row.col.f32.bf16.bf16.f32 "
        "{%0,%1,%2,%3}, {%4,%5,%6,%7}, {%8,%9}, {%0,%1,%2,%3};"
        : "+f"(d[0]), "+f"(d[1]), "+f"(d[2]), "+f"(d[3])
        : "r"(a[0]), "r"(a[1]), "r"(a[2]), "r"(a[3]), "r"(b[0]), "r"(b[1]));
}

struct alignas(16) BF8 { __nv_bfloat16 v[8]; };
__device__ __forceinline__ void split8(const float* f, BF8& hi, BF8& lo) {
    #pragma unroll
    for (int i = 0; i < 8; ++i) {
        __nv_bfloat16 h = __float2bfloat16(f[i]);
        hi.v[i] = h;
        lo.v[i] = __float2bfloat16(f[i] - __bfloat162float(h));
    }
}

// ---------------- smem layout (per pipeline stage) ----------------
#define A_STRIDE_B 80
#define BNT_STRIDE_B 80
#define BNN_STRIDE_B 144
#define OFF_AHI 0
#define OFF_ALO 10240
#define OFF_BHI 20480
#define OFF_BLO 25600
#define STAGE_BYTES 30720
#define SMEM_DYN (2 * STAGE_BYTES)   // 61440

// epilogue/flag bits
#define F_TRANS   1
#define F_EXP     2
#define F_ADDNORM 4
#define F_NORMA   8

// ---------------- universal pipelined bf16-split mma.sync GEMM ----------------
// C[M,N] = alpha * A[M,K] @ op(B) (+bias[col]) (+addScale*Add[row,col]*AddInv[row])
// F_EXP: C = exp(val); per-row tile partial sums -> Psum[(zP+row)*gridDim.x + bx]
// F_NORMA: A rows scaled by AInv[zNi+row] during load AND written back to gmem.
__global__ void __launch_bounds__(256, 2) k_mma_gemm(
    const float* __restrict__ A, const float* __restrict__ B,
    const float* __restrict__ bias, const float* __restrict__ Add,
    const float* __restrict__ AddInv, const float* __restrict__ AInv,
    float* __restrict__ C, float* __restrict__ Psum,
    int K, int lda, int ldb, int ldc, int ldadd, int zdiv,
    long long sA1, long long sA0, long long sB1, long long sB0,
    long long sC1, long long sC0, long long sAdd1, long long sAdd0,
    long long sAi1, long long sAi0, long long sNi1, long long sNi0,
    long long sP1, long long sP0,
    float alpha, float addScale, int flags)
{
    extern __shared__ __align__(16) uint8_t smem[];
    const uint32_t sb = smem_to_u32(smem);

    const int tid = threadIdx.x;
    const int wid = tid >> 5;
    const int lane = tid & 31;

    const int z = blockIdx.z;
    const int z1 = z / zdiv, z0 = z % zdiv;
    A += z1 * sA1 + z0 * sA0;
    B += z1 * sB1 + z0 * sB0;
    C += z1 * sC1 + z0 * sC0;
    if (Add) Add += z1 * sAdd1 + z0 * sAdd0;
    const long long ziAdd = z1 * sAi1 + z0 * sAi0;   // AddInv row base
    const long long ziN   = z1 * sNi1 + z0 * sNi0;   // AInv row base
    const long long ziP   = z1 * sP1  + z0 * sP0;    // Psum row base

    const int m0 = blockIdx.y * 128;
    const int n0 = blockIdx.x * 64;

    const int wm0 = (wid >> 1) * 32;
    const int wn0 = (wid & 1) * 32;

    // ldmatrix per-lane offsets (within one stage buffer)
    const uint32_t aLane = (uint32_t)(wm0 + (lane & 15)) * A_STRIDE_B + ((lane >> 4) << 3) * 2;
    const uint32_t bLaneNT = (uint32_t)(wn0 + ((lane >> 1) & 8) + (lane & 7)) * BNT_STRIDE_B
                           + (uint32_t)(lane & 8) * 2;
    const uint32_t bLaneNN = (uint32_t)(lane & 15) * BNN_STRIDE_B
                           + (uint32_t)(wn0 + ((lane >> 1) & 8)) * 2;

    // global-load coords
    const int ar = tid >> 1, ahalf = tid & 1;   // A: 128 rows x 2 halves (16 floats)
    const int ntr = tid >> 2, ntq = tid & 3;    // B NT: 64 rows x 4 chunks (8 floats)
    const int nnr = tid >> 3, nnc = tid & 7;    // B NN: 32 rows x 8 chunks (8 floats)

    const float aScale = (flags & F_NORMA) ? AInv[ziN + m0 + ar] : 1.0f;

    float acc[2][4][4];
    #pragma unroll
    for (int i = 0; i < 2; ++i)
        #pragma unroll
        for (int j = 0; j < 4; ++j)
            #pragma unroll
            for (int e = 0; e < 4; ++e) acc[i][j][e] = 0.0f;

    float fA[16], fB[8];

#define LOAD_TILE(k0v) {                                                            \
        const float* srcA = A + (long long)(m0 + ar) * lda + (k0v) + ahalf * 16;    \
        *(float4*)(fA)      = *(const float4*)(srcA);                               \
        *(float4*)(fA + 4)  = *(const float4*)(srcA + 4);                           \
        *(float4*)(fA + 8)  = *(const float4*)(srcA + 8);                           \
        *(float4*)(fA + 12) = *(const float4*)(srcA + 12);                          \
        if (flags & F_NORMA) {                                                      \
            _Pragma("unroll") for (int e = 0; e < 16; ++e) fA[e] *= aScale;         \
            float* wb = const_cast<float*>(srcA);                                   \
            *(float4*)(wb)      = *(float4*)(fA);                                   \
            *(float4*)(wb + 4)  = *(float4*)(fA + 4);                               \
            *(float4*)(wb + 8)  = *(float4*)(fA + 8);                               \
            *(float4*)(wb + 12) = *(float4*)(fA + 12);                              \
        }                                                                           \
        if (flags & F_TRANS) {                                                      \
            const float* srcB = B + (long long)(n0 + ntr) * ldb + (k0v) + ntq * 8;  \
            *(float4*)(fB)     = *(const float4*)(srcB);                            \
            *(float4*)(fB + 4) = *(const float4*)(srcB + 4);                        \
        } else {                                                                    \
            const float* srcB = B + (long long)((k0v) + nnr) * ldb + n0 + nnc * 8;  \
            *(float4*)(fB)     = *(const float4*)(srcB);                            \
            *(float4*)(fB + 4) = *(const float4*)(srcB + 4);                        \
        }                                                                           \
    }

#define STORE_TILE(st) {                                                            \
        uint8_t* sp = smem + (st) * STAGE_BYTES;                                    \
        BF8 h0, l0, h1, l1;                                                         \
        split8(fA, h0, l0); split8(fA + 8, h1, l1);                                 \
        const uint32_t offA = (uint32_t)ar * A_STRIDE_B + ahalf * 32;               \
        *(uint4*)(sp + OFF_AHI + offA)      = *(const uint4*)&h0;                   \
        *(uint4*)(sp + OFF_AHI + offA + 16) = *(const uint4*)&h1;                   \
        *(uint4*)(sp + OFF_ALO + offA)      = *(const uint4*)&l0;                   \
        *(uint4*)(sp + OFF_ALO + offA + 16) = *(const uint4*)&l1;                   \
        BF8 hb, lb2; split8(fB, hb, lb2);                                           \
        const uint32_t offB = (flags & F_TRANS)                                     \
            ? (uint32_t)ntr * BNT_STRIDE_B + ntq * 16                               \
            : (uint32_t)nnr * BNN_STRIDE_B + nnc * 16;                              \
        *(uint4*)(sp + OFF_BHI + offB) = *(const uint4*)&hb;                        \
        *(uint4*)(sp + OFF_BLO + offB) = *(const uint4*)&lb2;                       \
    }

    const int nIter = K >> 5;   // BK = 32

    LOAD_TILE(0);
    STORE_TILE(0);
    __syncthreads();

    int cur = 0;
    for (int it = 0; it < nIter; ++it) {
        const bool hasNext = (it + 1 < nIter);
        if (hasNext) LOAD_TILE((it + 1) << 5);

        // ---- compute from stage cur: 2 k16 steps
        const uint32_t stb = sb + cur * STAGE_BYTES;
        #pragma unroll
        for (int kk = 0; kk < 2; ++kk) {
            uint32_t ahi[2][4], alo[2][4], bhi[2][4], blo[2][4];
            const uint32_t akk = aLane + (uint32_t)(kk * 16) * 2;
            #pragma unroll
            for (int mi = 0; mi < 2; ++mi) {
                const uint32_t off = akk + (uint32_t)(mi * 16) * A_STRIDE_B;
                ldmx4(ahi[mi], stb + OFF_AHI + off);
                ldmx4(alo[mi], stb + OFF_ALO + off);
            }
            if (flags & F_TRANS) {
                const uint32_t bkk = bLaneNT + (uint32_t)(kk * 16) * 2;
                #pragma unroll
                for (int nj = 0; nj < 2; ++nj) {
                    const uint32_t off = bkk + (uint32_t)(nj * 16) * BNT_STRIDE_B;
                    ldmx4(bhi[nj], stb + OFF_BHI + off);
                    ldmx4(blo[nj], stb + OFF_BLO + off);
                }
            } else {
                const uint32_t bkk = bLaneNN + (uint32_t)(kk * 16) * BNN_STRIDE_B;
                #pragma unroll
                for (int nj = 0; nj < 2; ++nj) {
                    const uint32_t off = bkk + (uint32_t)(nj * 16) * 2;
                    ldmx4t(bhi[nj], stb + OFF_BHI + off);
                    ldmx4t(blo[nj], stb + OFF_BLO + off);
                }
            }
            #pragma unroll
            for (int mi = 0; mi < 2; ++mi)
                #pragma unroll
                for (int jj = 0; jj < 4; ++jj) {
                    const uint32_t* bh = &bhi[jj >> 1][(jj & 1) * 2];
                    const uint32_t* bl = &blo[jj >> 1][(jj & 1) * 2];
                    mma16816(acc[mi][jj], ahi[mi], bh);
                    mma16816(acc[mi][jj], ahi[mi], bl);
                    mma16816(acc[mi][jj], alo[mi], bh);
                }
        }

        if (hasNext) STORE_TILE(cur ^ 1);
        __syncthreads();
        cur ^= 1;
    }

    // ---- epilogue ----
    const int g = lane >> 2, t = lane & 3;
    if (flags & F_EXP) {
        float* rowst = (float*)smem;   // [128][8] staging, stage area is free now
        float rp[2][2] = {{0.f, 0.f}, {0.f, 0.f}};
        #pragma unroll
        for (int mi = 0; mi < 2; ++mi) {
            const long long r0 = m0 + wm0 + mi * 16 + g;
            const long long r1 = r0 + 8;
            float ai0 = 0.f, ai1 = 0.f;
            if (flags & F_ADDNORM) {
                ai0 = AddInv[ziAdd + r0] * addScale;
                ai1 = AddInv[ziAdd + r1] * addScale;
            }
            #pragma unroll
            for (int jj = 0; jj < 4; ++jj) {
                const int col = n0 + wn0 + jj * 8 + t * 2;
                float v00 = acc[mi][jj][0] * alpha, v01 = acc[mi][jj][1] * alpha;
                float v10 = acc[mi][jj][2] * alpha, v11 = acc[mi][jj][3] * alpha;
                if (Add) {
                    v00 += ai0 * Add[r0 * ldadd + col];
                    v01 += ai0 * Add[r0 * ldadd + col + 1];
                    v10 += ai1 * Add[r1 * ldadd + col];
                    v11 += ai1 * Add[r1 * ldadd + col + 1];
                }
                const float e00 = __expf(v00), e01 = __expf(v01);
                const float e10 = __expf(v10), e11 = __expf(v11);
                *(float2*)&C[r0 * ldc + col] = make_float2(e00, e01);
                *(float2*)&C[r1 * ldc + col] = make_float2(e10, e11);
                rp[mi][0] += e00 + e01;
                rp[mi][1] += e10 + e11;
            }
        }
        const int cidx = (wid & 1) * 4 + t;
        rowst[(wm0 + g)      * 8 + cidx] = rp[0][0];
        rowst[(wm0 + g + 8)  * 8 + cidx] = rp[0][1];
        rowst[(wm0 + 16 + g) * 8 + cidx] = rp[1][0];
        rowst[(wm0 + 24 + g) * 8 + cidx] = rp[1][1];
        __syncthreads();
        if (tid < 128) {
            float s = 0.f;
            #pragma unroll
            for (int j = 0; j < 8; ++j) s += rowst[tid * 8 + j];
            Psum[(ziP + m0 + tid) * gridDim.x + blockIdx.x] = s;
        }
    } else {
        #pragma unroll
        for (int mi = 0; mi < 2; ++mi) {
            #pragma unroll
            for (int jj = 0; jj < 4; ++jj) {
                const long long r0 = m0 + wm0 + mi * 16 + g;
                const long long r1 = r0 + 8;
                const int col = n0 + wn0 + jj * 8 + t * 2;
                float v00 = acc[mi][jj][0] * alpha, v01 = acc[mi][jj][1] * alpha;
                float v10 = acc[mi][jj][2] * alpha, v11 = acc[mi][jj][3] * alpha;
                if (bias) { v00 += bias[col]; v01 += bias[col + 1];
                            v10 += bias[col]; v11 += bias[col + 1]; }
                if (Add) {
                    v00 += addScale * Add[r0 * ldadd + col];
                    v01 += addScale * Add[r0 * ldadd + col + 1];
                    v10 += addScale * Add[r1 * ldadd + col];
                    v11 += addScale * Add[r1 * ldadd + col + 1];
                }
                *(float2*)&C[r0 * ldc + col] = make_float2(v00, v01);
                *(float2*)&C[r1 * ldc + col] = make_float2(v10, v11);
            }
        }
    }
#undef LOAD_TILE
#undef STORE_TILE
}

// ---------------- row partial-sum reduction -> inverse ----------------
// part: [rows][32]; inv[row] = 1 / sum(part[row][:])
__global__ void __launch_bounds__(256) k_rowinv(
    const float* __restrict__ part, float* __restrict__ inv)
{
    const int row = blockIdx.x * 8 + (threadIdx.x >> 5);
    const int lane = threadIdx.x & 31;
    float s = part[(long long)row * 32 + lane];
    #pragma unroll
    for (int o = 16; o; o >>= 1) s += __shfl_xor_sync(0xFFFFFFFFu, s, o);
    if (lane == 0) inv[row] = 1.0f / s;
}

// ---------------- residual + LayerNorm ----------------
__global__ void __launch_bounds__(256) k_ln_res(
    const float* __restrict__ xin, const float* __restrict__ hs,
    const float* __restrict__ g, const float* __restrict__ be,
    float* __restrict__ out)
{
    long long row = blockIdx.x;
    const float* xr = xin + row * H_;
    const float* hr = hs + row * H_;
    float* orow = out + row * H_;
    int tid = threadIdx.x;
    __shared__ float red[256];

    float v[4];
    float s = 0.0f;
    #pragma unroll
    for (int i = 0; i < 4; ++i) { v[i] = xr[tid + i * 256] + hr[tid + i * 256]; s += v[i]; }
    red[tid] = s; __syncthreads();
    for (int t = 128; t > 0; t >>= 1) {
        if (tid < t) red[tid] += red[tid + t];
        __syncthreads();
    }
    float mu = red[0] * (1.0f / H_); __syncthreads();

    float var = 0.0f;
    #pragma unroll
    for (int i = 0; i < 4; ++i) { float d = v[i] - mu; var += d * d; }
    red[tid] = var; __syncthreads();
    for (int t = 128; t > 0; t >>= 1) {
        if (tid < t) red[tid] += red[tid + t];
        __syncthreads();
    }
    float inv = rsqrtf(red[0] * (1.0f / H_) + 1e-12f);
    #pragma unroll
    for (int i = 0; i < 4; ++i) {
        int c = tid + i * 256;
        orow[c] = (v[i] - mu) * inv * g[c] + be[c];
    }
}

// ---------------- host-side launch helper ----------------
static void launch_gemm(
    const float* A, const float* B, const float* bias, const float* Add,
    const float* AddInv, const float* AInv, float* C, float* Psum,
    int Mrows, int Ncols, int K, int lda, int ldb, int ldc, int ldadd,
    int Z, int zdiv,
    long long sA1, long long sA0, long long sB1, long long sB0,
    long long sC1, long long sC0, long long sAdd1, long long sAdd0,
    long long sAi1, long long sAi0, long long sNi1, long long sNi0,
    long long sP1, long long sP0,
    float alpha, float addScale, int flags)
{
    dim3 grid(Ncols / 64, Mrows / 128, Z);
    k_mma_gemm<<<grid, 256, SMEM_DYN>>>(
        A, B, bias, Add, AddInv, AInv, C, Psum,
        K, lda, ldb, ldc, ldadd, zdiv,
        sA1, sA0, sB1, sB0, sC1, sC0, sAdd1, sAdd0,
        sAi1, sAi0, sNi1, sNi0, sP1, sP0,
        alpha, addScale, flags);
}

extern "C" void kernel_launch(void* const* d_in, const int* in_sizes, int n_in,
                              void* d_out, int out_size)
{
    const float* hs  = (const float*)d_in[0];
    const float* mc  = (const float*)d_in[1];
    const float* Wq  = (const float*)d_in[2];  const float* bq  = (const float*)d_in[3];
    const float* Wk  = (const float*)d_in[4];  const float* bk  = (const float*)d_in[5];
    const float* Wv  = (const float*)d_in[6];  const float* bv  = (const float*)d_in[7];
    const float* Wmq = (const float*)d_in[8];  const float* bmq = (const float*)d_in[9];
    const float* Wmk = (const float*)d_in[10]; const float* bmk = (const float*)d_in[11];
    const float* Wc  = (const float*)d_in[12]; const float* bc  = (const float*)d_in[13];
    const float* Wf  = (const float*)d_in[14]; const float* bf  = (const float*)d_in[15];
    const float* lg  = (const float*)d_in[16]; const float* lb  = (const float*)d_in[17];

    float* out   = (float*)d_out;                        // [B,S,H]
    float* probs = out + (long long)B_ * S_ * H_;        // [B,NH,S,S]

    float *q, *k, *v, *mq, *mk, *med, *cat, *x, *part, *minv, *pinv;
    cudaGetSymbolAddress((void**)&q,    g_q);
    cudaGetSymbolAddress((void**)&k,    g_k);
    cudaGetSymbolAddress((void**)&v,    g_v);
    cudaGetSymbolAddress((void**)&mq,   g_mq);
    cudaGetSymbolAddress((void**)&mk,   g_mk);
    cudaGetSymbolAddress((void**)&med,  g_med);
    cudaGetSymbolAddress((void**)&cat,  g_cat);
    cudaGetSymbolAddress((void**)&x,    g_x);
    cudaGetSymbolAddress((void**)&part, g_part);
    cudaGetSymbolAddress((void**)&minv, g_minv);
    cudaGetSymbolAddress((void**)&pinv, g_pinv);

    cudaFuncSetAttribute(k_mma_gemm, cudaFuncAttributeMaxDynamicSharedMemorySize, SMEM_DYN);

    const int rows = B_ * S_;            // 4096
    const long long SS = (long long)S_ * S_;
    const long long SH = (long long)S_ * H_;
    const long long SM = (long long)S_ * M_;

    // Q, K, V projections (NN)
    launch_gemm(hs, Wq, bq, 0, 0, 0, q, 0, rows, H_, H_, H_, H_, H_, 0, 1, 1,
                0,0, 0,0, 0,0, 0,0, 0,0, 0,0, 0,0, 1.0f, 0.0f, 0);
    launch_gemm(hs, Wk, bk, 0, 0, 0, k, 0, rows, H_, H_, H_, H_, H_, 0, 1, 1,
                0,0, 0,0, 0,0, 0,0, 0,0, 0,0, 0,0, 1.0f, 0.0f, 0);
    launch_gemm(hs, Wv, bv, 0, 0, 0, v, 0, rows, H_, H_, H_, H_, H_, 0, 1, 1,
                0,0, 0,0, 0,0, 0,0, 0,0, 0,0, 0,0, 1.0f, 0.0f, 0);

    // medical projections (NN)
    launch_gemm(hs, Wmq, bmq, 0, 0, 0, mq, 0, rows, M_, H_, H_, M_, M_, 0, 1, 1,
                0,0, 0,0, 0,0, 0,0, 0,0, 0,0, 0,0, 1.0f, 0.0f, 0);
    launch_gemm(mc, Wmk, bmk, 0, 0, 0, mk, 0, rows, M_, H_, H_, M_, M_, 0, 1, 1,
                0,0, 0,0, 0,0, 0,0, 0,0, 0,0, 0,0, 1.0f, 0.0f, 0);

    // med scores: exp(mq @ mk^T) -> g_med, partial row sums -> g_part  (NT, per batch)
    launch_gemm(mq, mk, 0, 0, 0, 0, med, part, S_, S_, M_, M_, M_, S_, 0, B_, 1,
                SM,0, SM,0, SS,0, 0,0, 0,0, 0,0, (long long)S_,0,
                1.0f, 0.0f, F_TRANS | F_EXP);
    k_rowinv<<<rows / 8, 256>>>(part, minv);

    // attn scores: exp(qk/8 + 0.3*medexp*minv) -> probs, partial sums (NT, per b,h)
    launch_gemm(q, k, 0, med, minv, 0, probs, part, S_, S_, D_, H_, H_, S_, S_,
                B_ * NH_, NH_,
                SH, D_, SH, D_, NH_ * SS, SS, SS, 0,
                (long long)S_, 0, 0, 0,
                (long long)NH_ * S_, (long long)S_,
                0.125f, 0.3f, F_TRANS | F_EXP | F_ADDNORM);
    k_rowinv<<<(B_ * NH_ * S_) / 8, 256>>>(part, pinv);

    // ctx = (probs * pinv) @ v -> cat[:, 0:1024]; normalized probs written back (NN)
    launch_gemm(probs, v, 0, 0, 0, pinv, cat, 0, S_, D_, S_, S_, H_, CAT_, 0,
                B_ * NH_, NH_,
                NH_ * SS, SS, SH, D_, (long long)S_ * CAT_, D_, 0, 0,
                0,0, (long long)NH_ * S_, (long long)S_, 0,0,
                1.0f, 0.0f, F_NORMA);

    // clin = ctx @ Wc + bc -> cat[:, 1024:1536]  (NN)
    launch_gemm(cat, Wc, bc, 0, 0, 0, cat + H_, 0, rows, M_, H_, CAT_, M_, CAT_, 0, 1, 1,
                0,0, 0,0, 0,0, 0,0, 0,0, 0,0, 0,0, 1.0f, 0.0f, 0);

    // final = cat @ Wf + bf  (NN)
    launch_gemm(cat, Wf, bf, 0, 0, 0, x, 0, rows, H_, CAT_, CAT_, H_, H_, 0, 1, 1,
                0,0, 0,0, 0,0, 0,0, 0,0, 0,0, 0,0, 1.0f, 0.0f, 0);

    // residual + layernorm -> out
    k_ln_res<<<rows, 256>>>(x, hs, lg, lb, out);
}